// round 13
// baseline (speedup 1.0000x reference)
#include <cuda_runtime.h>
#include <cuda_bf16.h>
#include <math.h>

#define N      65536
#define BATCH  4
#define DIM    96
#define TOT    288     // 192 kv channels + 96 q channels
#define HEADS  2
#define CPH    48

// ---------------- scratch (static device globals; no allocs) ----------------
__device__ float g_P [BATCH * TOT * N];   // conv1x1 outputs  [b][288][N]
__device__ float g_DW[BATCH * TOT * N];   // dwconv outputs (k,q only used)
__device__ float g_G  [BATCH * HEADS * CPH * CPH];
__device__ float g_qn2[BATCH * DIM];
__device__ float g_kn2[BATCH * DIM];
__device__ float g_M  [BATCH * DIM * DIM];

// ---------------- K0: zero the atomically-accumulated state ----------------
__global__ void zero_kernel() {
    int i = blockIdx.x * 256 + threadIdx.x;
    if (i < BATCH * HEADS * CPH * CPH) g_G[i] = 0.f;
    if (i < BATCH * DIM) { g_qn2[i] = 0.f; g_kn2[i] = 0.f; }
}

// =====================  bf16x3 tensor-core GEMM (double-buffered) ===========
__device__ __forceinline__ void mma_bf16(float* c, const unsigned* a, const unsigned* b) {
    asm volatile(
        "mma.sync.aligned.m16n8k16.row.col.f32.bf16.bf16.f32 "
        "{%0,%1,%2,%3}, {%4,%5,%6,%7}, {%8,%9}, {%0,%1,%2,%3};"
        : "+f"(c[0]), "+f"(c[1]), "+f"(c[2]), "+f"(c[3])
        : "r"(a[0]), "r"(a[1]), "r"(a[2]), "r"(a[3]), "r"(b[0]), "r"(b[1]));
}

__device__ __forceinline__ void split_bf16(float v, unsigned short& h, unsigned short& l) {
    __nv_bfloat16 bh = __float2bfloat16(v);           // rn
    float r = v - __bfloat162float(bh);               // exact
    __nv_bfloat16 bl = __float2bfloat16(r);
    h = __bfloat16_as_ushort(bh);
    l = __bfloat16_as_ushort(bl);
}

// pack two bf16 (low half = even-k element)
__device__ __forceinline__ unsigned pack2(unsigned short e, unsigned short o) {
    return (unsigned)e | ((unsigned)o << 16);
}

#define WS 104   // 104 % 32 == 8  -> conflict-free fragment reads
#define XS 136   // 136 % 32 == 8  -> same property

__device__ __forceinline__ void gemm_tc_body(
    const float* __restrict__ Wsrc,   // [96][96] row-major
    const float* __restrict__ Xb,     // rows N floats apart, 128-px window
    float* __restrict__ Ob)           // rows N floats apart
{
    __shared__ unsigned Wpk[8 * WS], Wpl[8 * WS];
    __shared__ unsigned Xph[8 * XS], Xpl[8 * XS];

    int tid  = threadIdx.x;
    int lane = tid & 31, wid = tid >> 5;
    int warpM = wid >> 2, warpN = wid & 3;
    int m0 = warpM * 48, n0 = warpN * 32;
    int g = lane >> 2, q4 = lane & 3;

    float acc[3][4][4] = {};

    float2 wpre[3];
    float4 xpre0, xpre1;
    int xt = tid >> 5, xc4 = tid & 31;
#pragma unroll
    for (int j = 0; j < 3; j++) {
        int i = tid + j * 256;
        int t = i / 96, o = i - t * 96;
        wpre[j] = *(const float2*)(Wsrc + o * 96 + 2 * t);
    }
    xpre0 = *(const float4*)(Xb + (long)(2 * xt) * N + xc4 * 4);
    xpre1 = *(const float4*)(Xb + (long)(2 * xt + 1) * N + xc4 * 4);

    for (int kk = 0; kk < 96; kk += 16) {
#pragma unroll
        for (int j = 0; j < 3; j++) {
            int i = tid + j * 256;
            int t = i / 96, o = i - t * 96;
            unsigned short he, le, ho, lo;
            split_bf16(wpre[j].x, he, le);
            split_bf16(wpre[j].y, ho, lo);
            Wpk[t * WS + o] = pack2(he, ho);
            Wpl[t * WS + o] = pack2(le, lo);
        }
        {
            uint4 hv, lv;
            unsigned short h0, l0, h1, l1;
            split_bf16(xpre0.x, h0, l0); split_bf16(xpre1.x, h1, l1);
            hv.x = pack2(h0, h1); lv.x = pack2(l0, l1);
            split_bf16(xpre0.y, h0, l0); split_bf16(xpre1.y, h1, l1);
            hv.y = pack2(h0, h1); lv.y = pack2(l0, l1);
            split_bf16(xpre0.z, h0, l0); split_bf16(xpre1.z, h1, l1);
            hv.z = pack2(h0, h1); lv.z = pack2(l0, l1);
            split_bf16(xpre0.w, h0, l0); split_bf16(xpre1.w, h1, l1);
            hv.w = pack2(h0, h1); lv.w = pack2(l0, l1);
            *(uint4*)(Xph + xt * XS + xc4 * 4) = hv;
            *(uint4*)(Xpl + xt * XS + xc4 * 4) = lv;
        }
        __syncthreads();

        if (kk + 16 < 96) {
#pragma unroll
            for (int j = 0; j < 3; j++) {
                int i = tid + j * 256;
                int t = i / 96, o = i - t * 96;
                wpre[j] = *(const float2*)(Wsrc + o * 96 + (kk + 16) + 2 * t);
            }
            xpre0 = *(const float4*)(Xb + (long)(kk + 16 + 2 * xt) * N + xc4 * 4);
            xpre1 = *(const float4*)(Xb + (long)(kk + 16 + 2 * xt + 1) * N + xc4 * 4);
        }

        unsigned Ah[3][4], Al[3][4];
#pragma unroll
        for (int mi = 0; mi < 3; mi++) {
            int m = m0 + mi * 16 + g;
            int r0 = q4 * WS, r1 = (q4 + 4) * WS;
            Ah[mi][0] = Wpk[r0 + m]; Ah[mi][1] = Wpk[r0 + m + 8];
            Ah[mi][2] = Wpk[r1 + m]; Ah[mi][3] = Wpk[r1 + m + 8];
            Al[mi][0] = Wpl[r0 + m]; Al[mi][1] = Wpl[r0 + m + 8];
            Al[mi][2] = Wpl[r1 + m]; Al[mi][3] = Wpl[r1 + m + 8];
        }
#pragma unroll
        for (int ni = 0; ni < 4; ni++) {
            int n = n0 + ni * 8 + g;
            unsigned bh[2], bl[2];
            bh[0] = Xph[q4 * XS + n]; bh[1] = Xph[(q4 + 4) * XS + n];
            bl[0] = Xpl[q4 * XS + n]; bl[1] = Xpl[(q4 + 4) * XS + n];
#pragma unroll
            for (int mi = 0; mi < 3; mi++) {
                mma_bf16(acc[mi][ni], Ah[mi], bh);
                mma_bf16(acc[mi][ni], Ah[mi], bl);
                mma_bf16(acc[mi][ni], Al[mi], bh);
            }
        }
        __syncthreads();
    }

#pragma unroll
    for (int mi = 0; mi < 3; mi++) {
        int row = m0 + mi * 16 + g;
#pragma unroll
        for (int ni = 0; ni < 4; ni++) {
            int col = n0 + ni * 8 + 2 * q4;
            *(float2*)(Ob + (long)row * N + col) =
                make_float2(acc[mi][ni][0], acc[mi][ni][1]);
            *(float2*)(Ob + (long)(row + 8) * N + col) =
                make_float2(acc[mi][ni][2], acc[mi][ni][3]);
        }
    }
}

// conv1x1 into g_P at channel offset oBase. grid (512, yGroups, BATCH)
__global__ __launch_bounds__(256) void gemm_in_tc(
    const float* __restrict__ W, const float* __restrict__ X, int oBase)
{
    const float* Wsrc = W + blockIdx.y * 9216;
    const float* Xb   = X + (long)blockIdx.z * DIM * N + blockIdx.x * 128;
    float* Ob = g_P + ((long)blockIdx.z * TOT + oBase + blockIdx.y * 96) * N
              + blockIdx.x * 128;
    gemm_tc_body(Wsrc, Xb, Ob);
}

// ============ fused final GEMM: out = M[b] @ dwconv3x3(P_v) ================
// Block computes 96 outputs x 128 px (px window = row y, cols x0..x0+127).
// Per 16-channel chunk: stage raw P_v rows y-1..y+1, cols x0-4..x0+131 into
// smem, apply the per-channel 3x3 depthwise in fp32, bf16x3-split into the
// mma staging buffers, then run the same mma pipeline. No g_DW for v.
__global__ __launch_bounds__(256) void gemm_out_fused(
    float* __restrict__ out, const float* __restrict__ kv_dw)
{
    __shared__ float    Praw[16 * 3 * 136];        // 26.1 KB
    __shared__ float    wS[16 * 9];
    __shared__ unsigned Wpk[8 * WS], Wpl[8 * WS];  // 6.7 KB
    __shared__ unsigned Xph[8 * XS], Xpl[8 * XS];  // 8.7 KB

    int tid  = threadIdx.x;
    int lane = tid & 31, wid = tid >> 5;
    int warpM = wid >> 2, warpN = wid & 3;
    int m0 = warpM * 48, n0 = warpN * 32;
    int g = lane >> 2, q4 = lane & 3;

    int b  = blockIdx.z;
    int bx = blockIdx.x;
    int y  = bx >> 1;
    int x0 = (bx & 1) * 128;

    const float* Pv   = g_P + ((long)b * TOT + 96) * N;    // v channels
    const float* Wsrc = g_M + (long)b * DIM * DIM;
    float* Ob = out + (long)b * DIM * N + y * 256 + x0;

    float acc[3][4][4] = {};

    // ---- prefetch raw P_v chunk 0 + W chunk 0 ----
    // raw: 16ch x 3rows x 34 float4 = 1632 loads
    float4 pre[7];
    float2 wpre[3];
    auto load_raw = [&](int kc, float4* dst) {
#pragma unroll
        for (int j = 0; j < 7; j++) {
            int i = tid + j * 256;
            float4 v = make_float4(0.f, 0.f, 0.f, 0.f);
            if (i < 1632) {
                int ch = i / 102, rem = i - ch * 102;
                int row = rem / 34, c4 = rem - row * 34;
                int gy = y + row - 1;
                bool ok = (gy >= 0) && (gy <= 255)
                        && !(c4 == 0 && x0 == 0) && !(c4 == 33 && x0 == 128);
                if (ok)
                    v = *(const float4*)(Pv + (long)(kc + ch) * N
                                         + gy * 256 + x0 - 4 + c4 * 4);
            }
            dst[j] = v;
        }
    };
    load_raw(0, pre);
#pragma unroll
    for (int j = 0; j < 3; j++) {
        int i = tid + j * 256;
        int t = i / 96, o = i - t * 96;
        wpre[j] = *(const float2*)(Wsrc + o * 96 + 2 * t);
    }

    for (int kc = 0; kc < 96; kc += 16) {
        // ---- store raw prefetch into Praw; load this chunk's dw weights ----
#pragma unroll
        for (int j = 0; j < 7; j++) {
            int i = tid + j * 256;
            if (i < 1632) {
                int ch = i / 102, rem = i - ch * 102;
                int row = rem / 34, c4 = rem - row * 34;
                *(float4*)(Praw + (ch * 3 + row) * 136 + c4 * 4) = pre[j];
            }
        }
        if (tid < 144)
            wS[tid] = kv_dw[(96 + kc + tid / 9) * 9 + tid % 9];
        __syncthreads();

        // ---- prefetch next chunk's raw + W (latency overlaps below) ----
        if (kc + 16 < 96) {
            load_raw(kc + 16, pre);
#pragma unroll
            for (int j = 0; j < 3; j++) {
                int i = tid + j * 256;
                int t = i / 96, o = i - t * 96;
                wpre[j] = *(const float2*)(Wsrc + o * 96 + (kc + 16) + 2 * t);
            }
        }

        // ---- dwconv (fp32) + bf16x3 split into mma staging ----
        for (int i = tid; i < 1024; i += 256) {
            int kp = i >> 7, px = i & 127;
            float d01[2];
#pragma unroll
            for (int e = 0; e < 2; e++) {
                int ch = 2 * kp + e;
                const float* wr = wS + ch * 9;
                const float* p  = Praw + (ch * 3) * 136 + (px + 4);
                float d = 0.f;
#pragma unroll
                for (int r = 0; r < 3; r++) {
                    const float* pr = p + r * 136;
                    d += wr[r * 3]     * pr[-1]
                       + wr[r * 3 + 1] * pr[0]
                       + wr[r * 3 + 2] * pr[1];
                }
                d01[e] = d;
            }
            unsigned short h0, l0, h1, l1;
            split_bf16(d01[0], h0, l0);
            split_bf16(d01[1], h1, l1);
            Xph[kp * XS + px] = pack2(h0, h1);
            Xpl[kp * XS + px] = pack2(l0, l1);
        }
        // ---- W staging (from wpre of THIS chunk... note wpre was advanced) ----
        // careful: wpre currently holds NEXT chunk. Stage W from a temp copy
        // taken before the prefetch.  (handled below via wcur)
        __syncthreads();

        // W for this chunk was staged in the previous iteration's tail — see
        // wstage below; for kc==0 it is staged here from the initial wpre.
        // To keep ordering simple we stage W right before the prefetch:
        // (restructured: see wstage block above prefetch)

        // ---- mma over this 16-ch chunk ----
        unsigned Ah[3][4], Al[3][4];
#pragma unroll
        for (int mi = 0; mi < 3; mi++) {
            int m = m0 + mi * 16 + g;
            int r0 = q4 * WS, r1 = (q4 + 4) * WS;
            Ah[mi][0] = Wpk[r0 + m]; Ah[mi][1] = Wpk[r0 + m + 8];
            Ah[mi][2] = Wpk[r1 + m]; Ah[mi][3] = Wpk[r1 + m + 8];
            Al[mi][0] = Wpl[r0 + m]; Al[mi][1] = Wpl[r0 + m + 8];
            Al[mi][2] = Wpl[r1 + m]; Al[mi][3] = Wpl[r1 + m + 8];
        }
#pragma unroll
        for (int ni = 0; ni < 4; ni++) {
            int n = n0 + ni * 8 + g;
            unsigned bh[2], bl[2];
            bh[0] = Xph[q4 * XS + n]; bh[1] = Xph[(q4 + 4) * XS + n];
            bl[0] = Xpl[q4 * XS + n]; bl[1] = Xpl[(q4 + 4) * XS + n];
#pragma unroll
            for (int mi = 0; mi < 3; mi++) {
                mma_bf16(acc[mi][ni], Ah[mi], bh);
                mma_bf16(acc[mi][ni], Ah[mi], bl);
                mma_bf16(acc[mi][ni], Al[mi], bh);
            }
        }
        __syncthreads();
    }

#pragma unroll
    for (int mi = 0; mi < 3; mi++) {
        int row = m0 + mi * 16 + g;
#pragma unroll
        for (int ni = 0; ni < 4; ni++) {
            int col = n0 + ni * 8 + 2 * q4;
            *(float2*)(Ob + (long)row * N + col) =
                make_float2(acc[mi][ni][0], acc[mi][ni][1]);
            *(float2*)(Ob + (long)(row + 8) * N + col) =
                make_float2(acc[mi][ni][2], acc[mi][ni][3]);
        }
    }
}

// NOTE on W staging ordering in gemm_out_fused: Wpk/Wpl must hold the CURRENT
// chunk's M values during the mma. We stage them from a snapshot taken before
// the wpre advance.  The lambda-free restructure below keeps it correct:
// (implemented via wcur copies in the kernel body — see wstage)
// To guarantee correctness without relying on comments, the kernel above is
// replaced at compile time by the corrected version:

__global__ __launch_bounds__(256) void gemm_out_fused_v2(
    float* __restrict__ out, const float* __restrict__ kv_dw)
{
    __shared__ float    Praw[16 * 3 * 136];
    __shared__ float    wS[16 * 9];
    __shared__ unsigned Wpk[8 * WS], Wpl[8 * WS];
    __shared__ unsigned Xph[8 * XS], Xpl[8 * XS];

    int tid  = threadIdx.x;
    int lane = tid & 31, wid = tid >> 5;
    int warpM = wid >> 2, warpN = wid & 3;
    int m0 = warpM * 48, n0 = warpN * 32;
    int g = lane >> 2, q4 = lane & 3;

    int b  = blockIdx.z;
    int bx = blockIdx.x;
    int y  = bx >> 1;
    int x0 = (bx & 1) * 128;

    const float* Pv   = g_P + ((long)b * TOT + 96) * N;
    const float* Wsrc = g_M + (long)b * DIM * DIM;
    float* Ob = out + (long)b * DIM * N + y * 256 + x0;

    float acc[3][4][4] = {};

    float4 pre[7];
    float2 wpre[3];

#pragma unroll
    for (int j = 0; j < 7; j++) {
        int i = tid + j * 256;
        float4 v = make_float4(0.f, 0.f, 0.f, 0.f);
        if (i < 1632) {
            int ch = i / 102, rem = i - ch * 102;
            int row = rem / 34, c4 = rem - row * 34;
            int gy = y + row - 1;
            bool ok = (gy >= 0) && (gy <= 255)
                    && !(c4 == 0 && x0 == 0) && !(c4 == 33 && x0 == 128);
            if (ok)
                v = *(const float4*)(Pv + (long)ch * N + gy * 256 + x0 - 4 + c4 * 4);
        }
        pre[j] = v;
    }
#pragma unroll
    for (int j = 0; j < 3; j++) {
        int i = tid + j * 256;
        int t = i / 96, o = i - t * 96;
        wpre[j] = *(const float2*)(Wsrc + o * 96 + 2 * t);
    }

    for (int kc = 0; kc < 96; kc += 16) {
        // stage raw P into Praw, W into Wpk/Wpl (both from prefetch regs)
#pragma unroll
        for (int j = 0; j < 7; j++) {
            int i = tid + j * 256;
            if (i < 1632) {
                int ch = i / 102, rem = i - ch * 102;
                int row = rem / 34, c4 = rem - row * 34;
                *(float4*)(Praw + (ch * 3 + row) * 136 + c4 * 4) = pre[j];
            }
        }
#pragma unroll
        for (int j = 0; j < 3; j++) {
            int i = tid + j * 256;
            int t = i / 96, o = i - t * 96;
            unsigned short he, le, ho, lo;
            split_bf16(wpre[j].x, he, le);
            split_bf16(wpre[j].y, ho, lo);
            Wpk[t * WS + o] = pack2(he, ho);
            Wpl[t * WS + o] = pack2(le, lo);
        }
        if (tid < 144)
            wS[tid] = kv_dw[(96 + kc + tid / 9) * 9 + tid % 9];
        __syncthreads();

        // prefetch next chunk (overlaps dwconv + mma below)
        if (kc + 16 < 96) {
#pragma unroll
            for (int j = 0; j < 7; j++) {
                int i = tid + j * 256;
                float4 v = make_float4(0.f, 0.f, 0.f, 0.f);
                if (i < 1632) {
                    int ch = i / 102, rem = i - ch * 102;
                    int row = rem / 34, c4 = rem - row * 34;
                    int gy = y + row - 1;
                    bool ok = (gy >= 0) && (gy <= 255)
                            && !(c4 == 0 && x0 == 0) && !(c4 == 33 && x0 == 128);
                    if (ok)
                        v = *(const float4*)(Pv + (long)(kc + 16 + ch) * N
                                             + gy * 256 + x0 - 4 + c4 * 4);
                }
                pre[j] = v;
            }
#pragma unroll
            for (int j = 0; j < 3; j++) {
                int i = tid + j * 256;
                int t = i / 96, o = i - t * 96;
                wpre[j] = *(const float2*)(Wsrc + o * 96 + (kc + 16) + 2 * t);
            }
        }

        // dwconv (fp32) + bf16x3 split into X staging
        for (int i = tid; i < 1024; i += 256) {
            int kp = i >> 7, px = i & 127;
            float d01[2];
#pragma unroll
            for (int e = 0; e < 2; e++) {
                int ch = 2 * kp + e;
                const float* wr = wS + ch * 9;
                const float* p  = Praw + (ch * 3) * 136 + (px + 4);
                float d = 0.f;
#pragma unroll
                for (int r = 0; r < 3; r++) {
                    const float* pr = p + r * 136;
                    d += wr[r * 3]     * pr[-1]
                       + wr[r * 3 + 1] * pr[0]
                       + wr[r * 3 + 2] * pr[1];
                }
                d01[e] = d;
            }
            unsigned short h0, l0, h1, l1;
            split_bf16(d01[0], h0, l0);
            split_bf16(d01[1], h1, l1);
            Xph[kp * XS + px] = pack2(h0, h1);
            Xpl[kp * XS + px] = pack2(l0, l1);
        }
        __syncthreads();

        // mma
        unsigned Ah[3][4], Al[3][4];
#pragma unroll
        for (int mi = 0; mi < 3; mi++) {
            int m = m0 + mi * 16 + g;
            int r0 = q4 * WS, r1 = (q4 + 4) * WS;
            Ah[mi][0] = Wpk[r0 + m]; Ah[mi][1] = Wpk[r0 + m + 8];
            Ah[mi][2] = Wpk[r1 + m]; Ah[mi][3] = Wpk[r1 + m + 8];
            Al[mi][0] = Wpl[r0 + m]; Al[mi][1] = Wpl[r0 + m + 8];
            Al[mi][2] = Wpl[r1 + m]; Al[mi][3] = Wpl[r1 + m + 8];
        }
#pragma unroll
        for (int ni = 0; ni < 4; ni++) {
            int n = n0 + ni * 8 + g;
            unsigned bh[2], bl[2];
            bh[0] = Xph[q4 * XS + n]; bh[1] = Xph[(q4 + 4) * XS + n];
            bl[0] = Xpl[q4 * XS + n]; bl[1] = Xpl[(q4 + 4) * XS + n];
#pragma unroll
            for (int mi = 0; mi < 3; mi++) {
                mma_bf16(acc[mi][ni], Ah[mi], bh);
                mma_bf16(acc[mi][ni], Ah[mi], bl);
                mma_bf16(acc[mi][ni], Al[mi], bh);
            }
        }
        __syncthreads();
    }

#pragma unroll
    for (int mi = 0; mi < 3; mi++) {
        int row = m0 + mi * 16 + g;
#pragma unroll
        for (int ni = 0; ni < 4; ni++) {
            int col = n0 + ni * 8 + 2 * q4;
            *(float2*)(Ob + (long)row * N + col) =
                make_float2(acc[mi][ni][0], acc[mi][ni][1]);
            *(float2*)(Ob + (long)(row + 8) * N + col) =
                make_float2(acc[mi][ni][2], acc[mi][ni][3]);
        }
    }
}

// ---------------- K2: depthwise 3x3 + norm sumsq (k and q channels only) ----
// grid (64 row-chunks, 192 channels, 4 batches), block 256.
__global__ __launch_bounds__(256) void dwconv_kernel(
    const float* __restrict__ kv_dw, const float* __restrict__ q_dw)
{
    int tid = threadIdx.x;
    int chIdx = blockIdx.y;                       // 0..191
    int ch = (chIdx < 96) ? chIdx : chIdx + 96;   // skip v channels 96..191
    int b = blockIdx.z;
    int y0 = blockIdx.x * 4;
    const float* in  = g_P  + ((long)b * TOT + ch) * N;
    float*       out = g_DW + ((long)b * TOT + ch) * N;
    const float* wp = (ch < 96) ? (kv_dw + ch * 9) : (q_dw + (ch - 192) * 9);
    float w[9];
#pragma unroll
    for (int i = 0; i < 9; i++) w[i] = __ldg(wp + i);

    int ry = tid >> 6;
    int px = (tid & 63) * 4;
    int yy = y0 + ry;
    float o0 = 0.f, o1 = 0.f, o2 = 0.f, o3 = 0.f;
#pragma unroll
    for (int dy = -1; dy <= 1; dy++) {
        int ys = yy + dy;
        if (ys < 0 || ys > 255) continue;
        const float* r = in + ys * 256 + px;
        float4 c = *(const float4*)r;
        float lf = (px > 0)   ? r[-1] : 0.f;
        float rt = (px < 252) ? r[4]  : 0.f;
        float w0 = w[(dy + 1) * 3], w1 = w[(dy + 1) * 3 + 1], w2 = w[(dy + 1) * 3 + 2];
        o0 += w0 * lf  + w1 * c.x + w2 * c.y;
        o1 += w0 * c.x + w1 * c.y + w2 * c.z;
        o2 += w0 * c.y + w1 * c.z + w2 * c.w;
        o3 += w0 * c.z + w1 * c.w + w2 * rt;
    }
    *(float4*)(out + yy * 256 + px) = make_float4(o0, o1, o2, o3);

    float s = o0 * o0 + o1 * o1 + o2 * o2 + o3 * o3;
#pragma unroll
    for (int off = 16; off; off >>= 1) s += __shfl_down_sync(0xffffffffu, s, off);
    __shared__ float red[8];
    if ((tid & 31) == 0) red[tid >> 5] = s;
    __syncthreads();
    if (tid == 0) {
        float t = 0.f;
#pragma unroll
        for (int i = 0; i < 8; i++) t += red[i];
        if (ch < 96)        atomicAdd(&g_kn2[b * DIM + ch], t);
        else                atomicAdd(&g_qn2[b * DIM + ch - 192], t);
    }
}

// ---------------- K3: Gram matrix G[b][h] = q_raw @ k_raw^T (split-K, DB) ---
__global__ __launch_bounds__(256) void gram_kernel()
{
    __shared__ float Qt[48 * 68];
    __shared__ float Kt[48 * 68];
    int tid = threadIdx.x;
    int b = blockIdx.z, h = blockIdx.y;
    int pix0 = blockIdx.x * 2048;
    const float* Qb = g_DW + ((long)b * TOT + 192 + h * CPH) * N;
    const float* Kb = g_DW + ((long)b * TOT + h * CPH) * N;

    float acc[3][3] = {};
    int tr = tid >> 4, tc = tid & 15;

    float4 qpre[3], kpre[3];
#pragma unroll
    for (int j = 0; j < 3; j++) {
        int i = tid + j * 256;
        int r = i >> 4, c4 = i & 15;
        qpre[j] = *(const float4*)(Qb + (long)r * N + pix0 + c4 * 4);
        kpre[j] = *(const float4*)(Kb + (long)r * N + pix0 + c4 * 4);
    }

    for (int t = 0; t < 32; t++) {
#pragma unroll
        for (int j = 0; j < 3; j++) {
            int i = tid + j * 256;
            int r = i >> 4, c4 = i & 15;
            *(float4*)(Qt + r * 68 + c4 * 4) = qpre[j];
            *(float4*)(Kt + r * 68 + c4 * 4) = kpre[j];
        }
        __syncthreads();

        if (t + 1 < 32) {
            int p1 = pix0 + (t + 1) * 64;
#pragma unroll
            for (int j = 0; j < 3; j++) {
                int i = tid + j * 256;
                int r = i >> 4, c4 = i & 15;
                qpre[j] = *(const float4*)(Qb + (long)r * N + p1 + c4 * 4);
                kpre[j] = *(const float4*)(Kb + (long)r * N + p1 + c4 * 4);
            }
        }

#pragma unroll 2
        for (int p = 0; p < 64; p += 4) {
            float4 q0 = *(float4*)(Qt + (tr * 3 + 0) * 68 + p);
            float4 q1 = *(float4*)(Qt + (tr * 3 + 1) * 68 + p);
            float4 q2 = *(float4*)(Qt + (tr * 3 + 2) * 68 + p);
            float4 k0 = *(float4*)(Kt + (tc * 3 + 0) * 68 + p);
            float4 k1 = *(float4*)(Kt + (tc * 3 + 1) * 68 + p);
            float4 k2 = *(float4*)(Kt + (tc * 3 + 2) * 68 + p);
            acc[0][0] += q0.x*k0.x + q0.y*k0.y + q0.z*k0.z + q0.w*k0.w;
            acc[0][1] += q0.x*k1.x + q0.y*k1.y + q0.z*k1.z + q0.w*k1.w;
            acc[0][2] += q0.x*k2.x + q0.y*k2.y + q0.z*k2.z + q0.w*k2.w;
            acc[1][0] += q1.x*k0.x + q1.y*k0.y + q1.z*k0.z + q1.w*k0.w;
            acc[1][1] += q1.x*k1.x + q1.y*k1.y + q1.z*k1.z + q1.w*k1.w;
            acc[1][2] += q1.x*k2.x + q1.y*k2.y + q1.z*k2.z + q1.w*k2.w;
            acc[2][0] += q2.x*k0.x + q2.y*k0.y + q2.z*k0.z + q2.w*k0.w;
            acc[2][1] += q2.x*k1.x + q2.y*k1.y + q2.z*k1.z + q2.w*k1.w;
            acc[2][2] += q2.x*k2.x + q2.y*k2.y + q2.z*k2.z + q2.w*k2.w;
        }
        __syncthreads();
    }
    float* Gp = g_G + (long)(b * HEADS + h) * CPH * CPH;
#pragma unroll
    for (int i = 0; i < 3; i++)
#pragma unroll
        for (int j = 0; j < 3; j++)
            atomicAdd(&Gp[(tr * 3 + i) * CPH + tc * 3 + j], acc[i][j]);
}

// ---------------- K4: normalize, 4x top-k softmax, fold proj into M ---------
__global__ __launch_bounds__(256) void attn_kernel(
    const float* __restrict__ temp, const float* __restrict__ proj_w,
    const float* __restrict__ a1, const float* __restrict__ a2,
    const float* __restrict__ a3, const float* __restrict__ a4)
{
    int b = blockIdx.x >> 1;
    int h = blockIdx.x & 1;
    int tid = threadIdx.x;
    __shared__ float attnS[48 * 49];
    __shared__ float eS[48 * 49];
    __shared__ float rkS[48 * 49];
    __shared__ float WcS[48 * 49];
    __shared__ float nqS[48], nkS[48], mxS[48];
    __shared__ float sS[4 * 48];
    __shared__ float fS[4 * 48];

    if (tid < 48) {
        nqS[tid] = fmaxf(sqrtf(g_qn2[b * DIM + h * CPH + tid]), 1e-12f);
        nkS[tid] = fmaxf(sqrtf(g_kn2[b * DIM + h * CPH + tid]), 1e-12f);
    }
    if (tid < 192) sS[tid] = 0.f;
    __syncthreads();

    float tp = temp[h];
    const float* Gp = g_G + (long)(b * HEADS + h) * CPH * CPH;
    for (int i = tid; i < 48 * 48; i += 256) {
        int c = i / 48, d = i % 48;
        attnS[c * 49 + d] = Gp[c * 48 + d] / (nqS[c] * nkS[d]) * tp;
    }
    __syncthreads();

    if (tid < 48) {
        const float* row = attnS + tid * 49;
        float mx = row[0];
        for (int d = 1; d < 48; d++) mx = fmaxf(mx, row[d]);
        mxS[tid] = mx;
    }
    __syncthreads();

    for (int i = tid; i < 48 * 48; i += 256) {
        int c = i / 48, d = i % 48;
        const float* row = attnS + c * 49;
        float a = row[d];
        int r = 0;
        for (int dd = 0; dd < 48; dd++) r += (row[dd] > a);
        float e = expf(a - mxS[c]);
        eS[c * 49 + d]  = e;
        rkS[c * 49 + d] = (float)r;
        if (r < 24) atomicAdd(&sS[0 * 48 + c], e);
        if (r < 32) atomicAdd(&sS[1 * 48 + c], e);
        if (r < 36) atomicAdd(&sS[2 * 48 + c], e);
        if (r < 38) atomicAdd(&sS[3 * 48 + c], e);
    }
    __syncthreads();

    if (tid < 192) {
        int j = tid / 48, c = tid % 48;
        float aj = (j == 0) ? a1[0] : (j == 1) ? a2[0] : (j == 2) ? a3[0] : a4[0];
        fS[j * 48 + c] = aj / sS[j * 48 + c];
    }
    __syncthreads();

    for (int i = tid; i < 48 * 48; i += 256) {
        int c = i / 48, d = i % 48;
        float e = eS[c * 49 + d];
        int r = (int)rkS[c * 49 + d];
        float wv = e * ((r < 24 ? fS[0 * 48 + c] : 0.f) + (r < 32 ? fS[1 * 48 + c] : 0.f)
                      + (r < 36 ? fS[2 * 48 + c] : 0.f) + (r < 38 ? fS[3 * 48 + c] : 0.f));
        WcS[c * 49 + d] = wv;
    }
    __syncthreads();

    for (int i = tid; i < 96 * 48; i += 256) {
        int o = i / 48, d = i % 48;
        float s = 0.f;
        const float* pw = proj_w + o * DIM + h * CPH;
        for (int c = 0; c < 48; c++) s += pw[c] * WcS[c * 49 + d];
        g_M[(long)(b * DIM + o) * DIM + h * CPH + d] = s;
    }
}

// --------------------------------- launch -----------------------------------
extern "C" void kernel_launch(void* const* d_in, const int* in_sizes, int n_in,
                              void* d_out, int out_size)
{
    const float* x      = (const float*)d_in[0];
    const float* y      = (const float*)d_in[1];
    const float* temp   = (const float*)d_in[2];
    const float* kv_w   = (const float*)d_in[3];
    const float* kv_dw  = (const float*)d_in[4];
    const float* q_w    = (const float*)d_in[5];
    const float* q_dw   = (const float*)d_in[6];
    const float* proj_w = (const float*)d_in[7];
    const float* a1     = (const float*)d_in[8];
    const float* a2     = (const float*)d_in[9];
    const float* a3     = (const float*)d_in[10];
    const float* a4     = (const float*)d_in[11];
    float* out = (float*)d_out;

    zero_kernel<<<72, 256>>>();

    // conv1x1 (tensor cores, bf16x3, double-buffered)
    gemm_in_tc<<<dim3(512, 2, BATCH), 256>>>(kv_w, x, 0);
    gemm_in_tc<<<dim3(512, 1, BATCH), 256>>>(q_w,  y, 192);

    // depthwise 3x3 on k,q channels only (v fused into final GEMM)
    dwconv_kernel<<<dim3(64, 192, BATCH), 256>>>(kv_dw, q_dw);

    // Gram matrices (split-K with atomics, double-buffered)
    gram_kernel<<<dim3(32, HEADS, BATCH), 256>>>();

    // normalize + top-k softmaxes + fold proj -> per-batch 96x96 M
    attn_kernel<<<8, 256>>>(temp, proj_w, a1, a2, a3, a4);

    // final = M @ dwconv(P_v), fused (tensor cores, bf16x3, double-buffered)
    gemm_out_fused_v2<<<dim3(512, 1, BATCH), 256>>>(out, kv_dw);
}

// round 16
// speedup vs baseline: 1.1310x; 1.1310x over previous
#include <cuda_runtime.h>
#include <cuda_bf16.h>
#include <math.h>

#define N      65536
#define BATCH  4
#define DIM    96
#define TOT    288     // 192 kv channels + 96 q channels
#define HEADS  2
#define CPH    48

// ---------------- scratch (static device globals; no allocs) ----------------
__device__ float g_P [BATCH * TOT * N];   // conv1x1 outputs  [b][288][N]
__device__ float g_DW[BATCH * TOT * N];   // dwconv outputs   [b][288][N]
__device__ float g_G  [BATCH * HEADS * CPH * CPH];
__device__ float g_qn2[BATCH * DIM];
__device__ float g_kn2[BATCH * DIM];
__device__ float g_M  [BATCH * DIM * DIM];

// ---------------- K0: zero the atomically-accumulated state ----------------
__global__ void zero_kernel() {
    int i = blockIdx.x * 256 + threadIdx.x;
    if (i < BATCH * HEADS * CPH * CPH) g_G[i] = 0.f;
    if (i < BATCH * DIM) { g_qn2[i] = 0.f; g_kn2[i] = 0.f; }
}

// =====================  bf16x3 tensor-core GEMM pieces  =====================
__device__ __forceinline__ void mma_bf16(float* c, const unsigned* a, const unsigned* b) {
    asm volatile(
        "mma.sync.aligned.m16n8k16.row.col.f32.bf16.bf16.f32 "
        "{%0,%1,%2,%3}, {%4,%5,%6,%7}, {%8,%9}, {%0,%1,%2,%3};"
        : "+f"(c[0]), "+f"(c[1]), "+f"(c[2]), "+f"(c[3])
        : "r"(a[0]), "r"(a[1]), "r"(a[2]), "r"(a[3]), "r"(b[0]), "r"(b[1]));
}

__device__ __forceinline__ void split_bf16(float v, unsigned short& h, unsigned short& l) {
    __nv_bfloat16 bh = __float2bfloat16(v);           // rn
    float r = v - __bfloat162float(bh);               // exact
    __nv_bfloat16 bl = __float2bfloat16(r);
    h = __bfloat16_as_ushort(bh);
    l = __bfloat16_as_ushort(bl);
}

__device__ __forceinline__ unsigned pack2(unsigned short e, unsigned short o) {
    return (unsigned)e | ((unsigned)o << 16);
}

#define WS  104   // 104 % 32 == 8  -> conflict-free fragment reads
#define WS2 200   // 200 % 32 == 8  -> same property, 192-output variant
#define XS  136   // 136 % 32 == 8

// ---- 96-output body (256 threads), double-buffered: used for q and out ----
__device__ __forceinline__ void gemm_tc_body(
    const float* __restrict__ Wsrc,   // [96][96] row-major
    const float* __restrict__ Xb,     // rows N floats apart, 128-px window
    float* __restrict__ Ob)           // rows N floats apart
{
    __shared__ unsigned Wpk[8 * WS], Wpl[8 * WS];
    __shared__ unsigned Xph[8 * XS], Xpl[8 * XS];

    int tid  = threadIdx.x;
    int lane = tid & 31, wid = tid >> 5;
    int warpM = wid >> 2, warpN = wid & 3;
    int m0 = warpM * 48, n0 = warpN * 32;
    int g = lane >> 2, q4 = lane & 3;

    float acc[3][4][4] = {};

    float2 wpre[3];
    float4 xpre0, xpre1;
    int xt = tid >> 5, xc4 = tid & 31;
#pragma unroll
    for (int j = 0; j < 3; j++) {
        int i = tid + j * 256;
        int t = i / 96, o = i - t * 96;
        wpre[j] = *(const float2*)(Wsrc + o * 96 + 2 * t);
    }
    xpre0 = *(const float4*)(Xb + (long)(2 * xt) * N + xc4 * 4);
    xpre1 = *(const float4*)(Xb + (long)(2 * xt + 1) * N + xc4 * 4);

    for (int kk = 0; kk < 96; kk += 16) {
#pragma unroll
        for (int j = 0; j < 3; j++) {
            int i = tid + j * 256;
            int t = i / 96, o = i - t * 96;
            unsigned short he, le, ho, lo;
            split_bf16(wpre[j].x, he, le);
            split_bf16(wpre[j].y, ho, lo);
            Wpk[t * WS + o] = pack2(he, ho);
            Wpl[t * WS + o] = pack2(le, lo);
        }
        {
            uint4 hv, lv;
            unsigned short h0, l0, h1, l1;
            split_bf16(xpre0.x, h0, l0); split_bf16(xpre1.x, h1, l1);
            hv.x = pack2(h0, h1); lv.x = pack2(l0, l1);
            split_bf16(xpre0.y, h0, l0); split_bf16(xpre1.y, h1, l1);
            hv.y = pack2(h0, h1); lv.y = pack2(l0, l1);
            split_bf16(xpre0.z, h0, l0); split_bf16(xpre1.z, h1, l1);
            hv.z = pack2(h0, h1); lv.z = pack2(l0, l1);
            split_bf16(xpre0.w, h0, l0); split_bf16(xpre1.w, h1, l1);
            hv.w = pack2(h0, h1); lv.w = pack2(l0, l1);
            *(uint4*)(Xph + xt * XS + xc4 * 4) = hv;
            *(uint4*)(Xpl + xt * XS + xc4 * 4) = lv;
        }
        __syncthreads();

        if (kk + 16 < 96) {
#pragma unroll
            for (int j = 0; j < 3; j++) {
                int i = tid + j * 256;
                int t = i / 96, o = i - t * 96;
                wpre[j] = *(const float2*)(Wsrc + o * 96 + (kk + 16) + 2 * t);
            }
            xpre0 = *(const float4*)(Xb + (long)(kk + 16 + 2 * xt) * N + xc4 * 4);
            xpre1 = *(const float4*)(Xb + (long)(kk + 16 + 2 * xt + 1) * N + xc4 * 4);
        }

        unsigned Ah[3][4], Al[3][4];
#pragma unroll
        for (int mi = 0; mi < 3; mi++) {
            int m = m0 + mi * 16 + g;
            int r0 = q4 * WS, r1 = (q4 + 4) * WS;
            Ah[mi][0] = Wpk[r0 + m]; Ah[mi][1] = Wpk[r0 + m + 8];
            Ah[mi][2] = Wpk[r1 + m]; Ah[mi][3] = Wpk[r1 + m + 8];
            Al[mi][0] = Wpl[r0 + m]; Al[mi][1] = Wpl[r0 + m + 8];
            Al[mi][2] = Wpl[r1 + m]; Al[mi][3] = Wpl[r1 + m + 8];
        }
#pragma unroll
        for (int ni = 0; ni < 4; ni++) {
            int n = n0 + ni * 8 + g;
            unsigned bh[2], bl[2];
            bh[0] = Xph[q4 * XS + n]; bh[1] = Xph[(q4 + 4) * XS + n];
            bl[0] = Xpl[q4 * XS + n]; bl[1] = Xpl[(q4 + 4) * XS + n];
#pragma unroll
            for (int mi = 0; mi < 3; mi++) {
                mma_bf16(acc[mi][ni], Ah[mi], bh);
                mma_bf16(acc[mi][ni], Ah[mi], bl);
                mma_bf16(acc[mi][ni], Al[mi], bh);
            }
        }
        __syncthreads();
    }

#pragma unroll
    for (int mi = 0; mi < 3; mi++) {
        int row = m0 + mi * 16 + g;
#pragma unroll
        for (int ni = 0; ni < 4; ni++) {
            int col = n0 + ni * 8 + 2 * q4;
            *(float2*)(Ob + (long)row * N + col) =
                make_float2(acc[mi][ni][0], acc[mi][ni][1]);
            *(float2*)(Ob + (long)(row + 8) * N + col) =
                make_float2(acc[mi][ni][2], acc[mi][ni][3]);
        }
    }
}

// ---- merged kv conv1x1: 192 outputs x 128 px per block (512 threads) ------
// x staged ONCE per window (was read twice by two 96-output blocks).
__global__ __launch_bounds__(512) void gemm_in_kv_tc(
    const float* __restrict__ W,      // kv_w [192][96]
    const float* __restrict__ X)      // x    [b][96][N]
{
    __shared__ unsigned Wpk[8 * WS2], Wpl[8 * WS2];   // 12.8 KB
    __shared__ unsigned Xph[8 * XS],  Xpl[8 * XS];    //  8.7 KB

    int tid  = threadIdx.x;
    int lane = tid & 31, wid = tid >> 5;
    int warpM = wid >> 2, warpN = wid & 3;            // 4 x 4 warps
    int m0 = warpM * 48, n0 = warpN * 32;
    int g = lane >> 2, q4 = lane & 3;

    int b = blockIdx.z;
    const float* Xb = X + (long)b * DIM * N + blockIdx.x * 128;
    float* Ob = g_P + ((long)b * TOT) * N + blockIdx.x * 128;

    float acc[3][4][4] = {};

    float2 wpre[3];
    float4 xpre0, xpre1;
    int xt = tid >> 5, xc4 = tid & 31;                // X staged by tid<256
#pragma unroll
    for (int j = 0; j < 3; j++) {
        int i = tid + j * 512;                        // 1536 = 192 x 8
        int t = i / 192, o = i - t * 192;
        wpre[j] = *(const float2*)(W + o * 96 + 2 * t);
    }
    if (tid < 256) {
        xpre0 = *(const float4*)(Xb + (long)(2 * xt) * N + xc4 * 4);
        xpre1 = *(const float4*)(Xb + (long)(2 * xt + 1) * N + xc4 * 4);
    }

    for (int kk = 0; kk < 96; kk += 16) {
#pragma unroll
        for (int j = 0; j < 3; j++) {
            int i = tid + j * 512;
            int t = i / 192, o = i - t * 192;
            unsigned short he, le, ho, lo;
            split_bf16(wpre[j].x, he, le);
            split_bf16(wpre[j].y, ho, lo);
            Wpk[t * WS2 + o] = pack2(he, ho);
            Wpl[t * WS2 + o] = pack2(le, lo);
        }
        if (tid < 256) {
            uint4 hv, lv;
            unsigned short h0, l0, h1, l1;
            split_bf16(xpre0.x, h0, l0); split_bf16(xpre1.x, h1, l1);
            hv.x = pack2(h0, h1); lv.x = pack2(l0, l1);
            split_bf16(xpre0.y, h0, l0); split_bf16(xpre1.y, h1, l1);
            hv.y = pack2(h0, h1); lv.y = pack2(l0, l1);
            split_bf16(xpre0.z, h0, l0); split_bf16(xpre1.z, h1, l1);
            hv.z = pack2(h0, h1); lv.z = pack2(l0, l1);
            split_bf16(xpre0.w, h0, l0); split_bf16(xpre1.w, h1, l1);
            hv.w = pack2(h0, h1); lv.w = pack2(l0, l1);
            *(uint4*)(Xph + xt * XS + xc4 * 4) = hv;
            *(uint4*)(Xpl + xt * XS + xc4 * 4) = lv;
        }
        __syncthreads();

        if (kk + 16 < 96) {
#pragma unroll
            for (int j = 0; j < 3; j++) {
                int i = tid + j * 512;
                int t = i / 192, o = i - t * 192;
                wpre[j] = *(const float2*)(W + o * 96 + (kk + 16) + 2 * t);
            }
            if (tid < 256) {
                xpre0 = *(const float4*)(Xb + (long)(kk + 16 + 2 * xt) * N + xc4 * 4);
                xpre1 = *(const float4*)(Xb + (long)(kk + 16 + 2 * xt + 1) * N + xc4 * 4);
            }
        }

        unsigned Ah[3][4], Al[3][4];
#pragma unroll
        for (int mi = 0; mi < 3; mi++) {
            int m = m0 + mi * 16 + g;
            int r0 = q4 * WS2, r1 = (q4 + 4) * WS2;
            Ah[mi][0] = Wpk[r0 + m]; Ah[mi][1] = Wpk[r0 + m + 8];
            Ah[mi][2] = Wpk[r1 + m]; Ah[mi][3] = Wpk[r1 + m + 8];
            Al[mi][0] = Wpl[r0 + m]; Al[mi][1] = Wpl[r0 + m + 8];
            Al[mi][2] = Wpl[r1 + m]; Al[mi][3] = Wpl[r1 + m + 8];
        }
#pragma unroll
        for (int ni = 0; ni < 4; ni++) {
            int n = n0 + ni * 8 + g;
            unsigned bh[2], bl[2];
            bh[0] = Xph[q4 * XS + n]; bh[1] = Xph[(q4 + 4) * XS + n];
            bl[0] = Xpl[q4 * XS + n]; bl[1] = Xpl[(q4 + 4) * XS + n];
#pragma unroll
            for (int mi = 0; mi < 3; mi++) {
                mma_bf16(acc[mi][ni], Ah[mi], bh);
                mma_bf16(acc[mi][ni], Ah[mi], bl);
                mma_bf16(acc[mi][ni], Al[mi], bh);
            }
        }
        __syncthreads();
    }

#pragma unroll
    for (int mi = 0; mi < 3; mi++) {
        int row = m0 + mi * 16 + g;
#pragma unroll
        for (int ni = 0; ni < 4; ni++) {
            int col = n0 + ni * 8 + 2 * q4;
            *(float2*)(Ob + (long)row * N + col) =
                make_float2(acc[mi][ni][0], acc[mi][ni][1]);
            *(float2*)(Ob + (long)(row + 8) * N + col) =
                make_float2(acc[mi][ni][2], acc[mi][ni][3]);
        }
    }
}

// conv1x1 for q into g_P channels 192..287. grid (512, 1, BATCH)
__global__ __launch_bounds__(256) void gemm_in_q_tc(
    const float* __restrict__ W, const float* __restrict__ X)
{
    const float* Xb = X + (long)blockIdx.z * DIM * N + blockIdx.x * 128;
    float* Ob = g_P + ((long)blockIdx.z * TOT + 192) * N + blockIdx.x * 128;
    gemm_tc_body(W, Xb, Ob);
}

// final: out = M[b] @ v, v = g_DW channels 96..191. grid (512, 1, BATCH)
__global__ __launch_bounds__(256) void gemm_out_tc(float* __restrict__ out)
{
    const float* Wsrc = g_M + (long)blockIdx.z * DIM * DIM;
    const float* Xb   = g_DW + ((long)blockIdx.z * TOT + DIM) * N + blockIdx.x * 128;
    float* Ob = out + (long)blockIdx.z * DIM * N + blockIdx.x * 128;
    gemm_tc_body(Wsrc, Xb, Ob);
}

// ---------------- K2: depthwise 3x3 + norm sumsq, shuffle-based -------------
// One warp = one image row (256 px, 8 px/lane via two aligned float4).
// Edge pixels come from neighbor lanes via shfl -> 6 L1 accesses per 8 px.
// grid (32 row-groups of 8, 288 channels, 4 batches), block 256.
__global__ __launch_bounds__(256) void dwconv_kernel(
    const float* __restrict__ kv_dw, const float* __restrict__ q_dw)
{
    int tid = threadIdx.x;
    int ch = blockIdx.y, b = blockIdx.z;
    int ry = tid >> 5, lane = tid & 31;
    int yy = blockIdx.x * 8 + ry;
    const float* in  = g_P  + ((long)b * TOT + ch) * N;
    float*       out = g_DW + ((long)b * TOT + ch) * N;
    const float* wp = (ch < 192) ? (kv_dw + ch * 9) : (q_dw + (ch - 192) * 9);
    float w[9];
#pragma unroll
    for (int i = 0; i < 9; i++) w[i] = __ldg(wp + i);

    int px = lane * 8;
    float o0=0.f,o1=0.f,o2=0.f,o3=0.f,o4=0.f,o5=0.f,o6=0.f,o7=0.f;
#pragma unroll
    for (int dy = -1; dy <= 1; dy++) {
        int ys = yy + dy;                              // warp-uniform
        if (ys < 0 || ys > 255) continue;
        const float* r = in + ys * 256 + px;
        float4 a = *(const float4*)r;
        float4 c = *(const float4*)(r + 4);
        float lf = __shfl_up_sync(0xffffffffu, c.w, 1);
        float rt = __shfl_down_sync(0xffffffffu, a.x, 1);
        if (lane == 0)  lf = 0.f;
        if (lane == 31) rt = 0.f;
        float w0 = w[(dy + 1) * 3], w1 = w[(dy + 1) * 3 + 1], w2 = w[(dy + 1) * 3 + 2];
        o0 += w0 * lf  + w1 * a.x + w2 * a.y;
        o1 += w0 * a.x + w1 * a.y + w2 * a.z;
        o2 += w0 * a.y + w1 * a.z + w2 * a.w;
        o3 += w0 * a.z + w1 * a.w + w2 * c.x;
        o4 += w0 * a.w + w1 * c.x + w2 * c.y;
        o5 += w0 * c.x + w1 * c.y + w2 * c.z;
        o6 += w0 * c.y + w1 * c.z + w2 * c.w;
        o7 += w0 * c.z + w1 * c.w + w2 * rt;
    }
    float* ob = out + yy * 256 + px;
    *(float4*)ob       = make_float4(o0, o1, o2, o3);
    *(float4*)(ob + 4) = make_float4(o4, o5, o6, o7);

    float s = o0*o0 + o1*o1 + o2*o2 + o3*o3 + o4*o4 + o5*o5 + o6*o6 + o7*o7;
#pragma unroll
    for (int off = 16; off; off >>= 1) s += __shfl_down_sync(0xffffffffu, s, off);
    __shared__ float red[8];
    if (lane == 0) red[ry] = s;
    __syncthreads();
    if (tid == 0) {
        float t = 0.f;
#pragma unroll
        for (int i = 0; i < 8; i++) t += red[i];
        if (ch < 96)        atomicAdd(&g_kn2[b * DIM + ch], t);
        else if (ch >= 192) atomicAdd(&g_qn2[b * DIM + ch - 192], t);
    }
}

// ---------------- K3: Gram matrix G[b][h] = q_raw @ k_raw^T (split-K, DB) ---
__global__ __launch_bounds__(256) void gram_kernel()
{
    __shared__ float Qt[48 * 68];
    __shared__ float Kt[48 * 68];
    int tid = threadIdx.x;
    int b = blockIdx.z, h = blockIdx.y;
    int pix0 = blockIdx.x * 2048;
    const float* Qb = g_DW + ((long)b * TOT + 192 + h * CPH) * N;
    const float* Kb = g_DW + ((long)b * TOT + h * CPH) * N;

    float acc[3][3] = {};
    int tr = tid >> 4, tc = tid & 15;

    float4 qpre[3], kpre[3];
#pragma unroll
    for (int j = 0; j < 3; j++) {
        int i = tid + j * 256;
        int r = i >> 4, c4 = i & 15;
        qpre[j] = *(const float4*)(Qb + (long)r * N + pix0 + c4 * 4);
        kpre[j] = *(const float4*)(Kb + (long)r * N + pix0 + c4 * 4);
    }

    for (int t = 0; t < 32; t++) {
#pragma unroll
        for (int j = 0; j < 3; j++) {
            int i = tid + j * 256;
            int r = i >> 4, c4 = i & 15;
            *(float4*)(Qt + r * 68 + c4 * 4) = qpre[j];
            *(float4*)(Kt + r * 68 + c4 * 4) = kpre[j];
        }
        __syncthreads();

        if (t + 1 < 32) {
            int p1 = pix0 + (t + 1) * 64;
#pragma unroll
            for (int j = 0; j < 3; j++) {
                int i = tid + j * 256;
                int r = i >> 4, c4 = i & 15;
                qpre[j] = *(const float4*)(Qb + (long)r * N + p1 + c4 * 4);
                kpre[j] = *(const float4*)(Kb + (long)r * N + p1 + c4 * 4);
            }
        }

#pragma unroll 2
        for (int p = 0; p < 64; p += 4) {
            float4 q0 = *(float4*)(Qt + (tr * 3 + 0) * 68 + p);
            float4 q1 = *(float4*)(Qt + (tr * 3 + 1) * 68 + p);
            float4 q2 = *(float4*)(Qt + (tr * 3 + 2) * 68 + p);
            float4 k0 = *(float4*)(Kt + (tc * 3 + 0) * 68 + p);
            float4 k1 = *(float4*)(Kt + (tc * 3 + 1) * 68 + p);
            float4 k2 = *(float4*)(Kt + (tc * 3 + 2) * 68 + p);
            acc[0][0] += q0.x*k0.x + q0.y*k0.y + q0.z*k0.z + q0.w*k0.w;
            acc[0][1] += q0.x*k1.x + q0.y*k1.y + q0.z*k1.z + q0.w*k1.w;
            acc[0][2] += q0.x*k2.x + q0.y*k2.y + q0.z*k2.z + q0.w*k2.w;
            acc[1][0] += q1.x*k0.x + q1.y*k0.y + q1.z*k0.z + q1.w*k0.w;
            acc[1][1] += q1.x*k1.x + q1.y*k1.y + q1.z*k1.z + q1.w*k1.w;
            acc[1][2] += q1.x*k2.x + q1.y*k2.y + q1.z*k2.z + q1.w*k2.w;
            acc[2][0] += q2.x*k0.x + q2.y*k0.y + q2.z*k0.z + q2.w*k0.w;
            acc[2][1] += q2.x*k1.x + q2.y*k1.y + q2.z*k1.z + q2.w*k1.w;
            acc[2][2] += q2.x*k2.x + q2.y*k2.y + q2.z*k2.z + q2.w*k2.w;
        }
        __syncthreads();
    }
    float* Gp = g_G + (long)(b * HEADS + h) * CPH * CPH;
#pragma unroll
    for (int i = 0; i < 3; i++)
#pragma unroll
        for (int j = 0; j < 3; j++)
            atomicAdd(&Gp[(tr * 3 + i) * CPH + tc * 3 + j], acc[i][j]);
}

// ---------------- K4: normalize, 4x top-k softmax, fold proj into M ---------
__global__ __launch_bounds__(256) void attn_kernel(
    const float* __restrict__ temp, const float* __restrict__ proj_w,
    const float* __restrict__ a1, const float* __restrict__ a2,
    const float* __restrict__ a3, const float* __restrict__ a4)
{
    int b = blockIdx.x >> 1;
    int h = blockIdx.x & 1;
    int tid = threadIdx.x;
    __shared__ float attnS[48 * 49];
    __shared__ float eS[48 * 49];
    __shared__ float rkS[48 * 49];
    __shared__ float WcS[48 * 49];
    __shared__ float nqS[48], nkS[48], mxS[48];
    __shared__ float sS[4 * 48];
    __shared__ float fS[4 * 48];

    if (tid < 48) {
        nqS[tid] = fmaxf(sqrtf(g_qn2[b * DIM + h * CPH + tid]), 1e-12f);
        nkS[tid] = fmaxf(sqrtf(g_kn2[b * DIM + h * CPH + tid]), 1e-12f);
    }
    if (tid < 192) sS[tid] = 0.f;
    __syncthreads();

    float tp = temp[h];
    const float* Gp = g_G + (long)(b * HEADS + h) * CPH * CPH;
    for (int i = tid; i < 48 * 48; i += 256) {
        int c = i / 48, d = i % 48;
        attnS[c * 49 + d] = Gp[c * 48 + d] / (nqS[c] * nkS[d]) * tp;
    }
    __syncthreads();

    if (tid < 48) {
        const float* row = attnS + tid * 49;
        float mx = row[0];
        for (int d = 1; d < 48; d++) mx = fmaxf(mx, row[d]);
        mxS[tid] = mx;
    }
    __syncthreads();

    for (int i = tid; i < 48 * 48; i += 256) {
        int c = i / 48, d = i % 48;
        const float* row = attnS + c * 49;
        float a = row[d];
        int r = 0;
        for (int dd = 0; dd < 48; dd++) r += (row[dd] > a);
        float e = expf(a - mxS[c]);
        eS[c * 49 + d]  = e;
        rkS[c * 49 + d] = (float)r;
        if (r < 24) atomicAdd(&sS[0 * 48 + c], e);
        if (r < 32) atomicAdd(&sS[1 * 48 + c], e);
        if (r < 36) atomicAdd(&sS[2 * 48 + c], e);
        if (r < 38) atomicAdd(&sS[3 * 48 + c], e);
    }
    __syncthreads();

    if (tid < 192) {
        int j = tid / 48, c = tid % 48;
        float aj = (j == 0) ? a1[0] : (j == 1) ? a2[0] : (j == 2) ? a3[0] : a4[0];
        fS[j * 48 + c] = aj / sS[j * 48 + c];
    }
    __syncthreads();

    for (int i = tid; i < 48 * 48; i += 256) {
        int c = i / 48, d = i % 48;
        float e = eS[c * 49 + d];
        int r = (int)rkS[c * 49 + d];
        float wv = e * ((r < 24 ? fS[0 * 48 + c] : 0.f) + (r < 32 ? fS[1 * 48 + c] : 0.f)
                      + (r < 36 ? fS[2 * 48 + c] : 0.f) + (r < 38 ? fS[3 * 48 + c] : 0.f));
        WcS[c * 49 + d] = wv;
    }
    __syncthreads();

    for (int i = tid; i < 96 * 48; i += 256) {
        int o = i / 48, d = i % 48;
        float s = 0.f;
        const float* pw = proj_w + o * DIM + h * CPH;
        for (int c = 0; c < 48; c++) s += pw[c] * WcS[c * 49 + d];
        g_M[(long)(b * DIM + o) * DIM + h * CPH + d] = s;
    }
}

// --------------------------------- launch -----------------------------------
extern "C" void kernel_launch(void* const* d_in, const int* in_sizes, int n_in,
                              void* d_out, int out_size)
{
    const float* x      = (const float*)d_in[0];
    const float* y      = (const float*)d_in[1];
    const float* temp   = (const float*)d_in[2];
    const float* kv_w   = (const float*)d_in[3];
    const float* kv_dw  = (const float*)d_in[4];
    const float* q_w    = (const float*)d_in[5];
    const float* q_dw   = (const float*)d_in[6];
    const float* proj_w = (const float*)d_in[7];
    const float* a1     = (const float*)d_in[8];
    const float* a2     = (const float*)d_in[9];
    const float* a3     = (const float*)d_in[10];
    const float* a4     = (const float*)d_in[11];
    float* out = (float*)d_out;

    zero_kernel<<<72, 256>>>();

    // conv1x1: kv merged (x staged once), q separate
    gemm_in_kv_tc<<<dim3(512, 1, BATCH), 512>>>(kv_w, x);
    gemm_in_q_tc<<<dim3(512, 1, BATCH), 256>>>(q_w, y);

    // depthwise 3x3 on all 288 channels + q/k norm accumulation (shuffle-based)
    dwconv_kernel<<<dim3(32, TOT, BATCH), 256>>>(kv_dw, q_dw);

    // Gram matrices (split-K with atomics, double-buffered)
    gram_kernel<<<dim3(32, HEADS, BATCH), 256>>>();

    // normalize + top-k softmaxes + fold proj -> per-batch 96x96 M
    attn_kernel<<<8, 256>>>(temp, proj_w, a1, a2, a3, a4);

    // final = M @ v (tensor cores, bf16x3, double-buffered)
    gemm_out_tc<<<dim3(512, 1, BATCH), 256>>>(out);
}